// round 2
// baseline (speedup 1.0000x reference)
#include <cuda_runtime.h>

#define NN 4096
#define DD 512
#define FF 512
#define HH 4
#define ALPHA 0.3f

// ---- scratch (no allocation allowed; __device__ globals) ----
__device__ float g_e[NN * FF];            // 8 MB
__device__ float g_feats[HH * NN * FF];   // 32 MB (feats + e, per head)
__device__ float g_s[HH * NN];
__device__ float g_t[HH * NN];
__device__ float g_rmax[HH * NN];
__device__ float g_invz[HH * NN];
__device__ float g_wu[HH * DD];
__device__ float g_wv[HH * DD];
__device__ float g_bu[HH];
__device__ float g_bv[HH];
__device__ float g_hpmax[HH];
__device__ float g_hmmin[HH];

__device__ __forceinline__ float warp_sum(float x) {
#pragma unroll
    for (int o = 16; o > 0; o >>= 1) x += __shfl_xor_sync(0xffffffffu, x, o);
    return x;
}

// ============================================================
// Generic 64x64x16 fp32 GEMM.
// MODE 0:  g_e    = (A + A2) @ B  + bias          (e projection)
// MODE 1:  g_feats[h] = A @ B[h] + bias[h] + g_e  (per-head feats2)
// ============================================================
template <int MODE>
__global__ __launch_bounds__(256) void gemm64(
    const float* __restrict__ A, const float* __restrict__ A2,
    const float* __restrict__ Bm, const float* __restrict__ bias)
{
    const float* B;
    const float* bi;
    float* C;
    if (MODE == 0) {
        B = Bm; bi = bias; C = g_e;
    } else {
        int h = blockIdx.z;
        B = Bm + (long)h * DD * FF;
        bi = bias + (long)h * FF;
        C = g_feats + (long)h * NN * FF;
    }

    __shared__ float As[16][64];
    __shared__ float Bs[16][64];

    int tid = threadIdx.x;
    int m0 = blockIdx.y * 64, f0 = blockIdx.x * 64;
    int arow = tid >> 2, akq = tid & 3;     // A load: 64 rows x 4 float4
    int brow = tid >> 4, bfq = tid & 15;    // B load: 16 rows x 16 float4
    int ty = tid >> 4, tx = tid & 15;       // 16x16 threads, 4x4 microtile

    float acc[4][4] = {};

    for (int k0 = 0; k0 < DD; k0 += 16) {
        float4 a4 = *(const float4*)(A + (long)(m0 + arow) * DD + k0 + akq * 4);
        if (MODE == 0) {
            float4 c4 = *(const float4*)(A2 + (long)(m0 + arow) * DD + k0 + akq * 4);
            a4.x += c4.x; a4.y += c4.y; a4.z += c4.z; a4.w += c4.w;
        }
        As[akq * 4 + 0][arow] = a4.x;
        As[akq * 4 + 1][arow] = a4.y;
        As[akq * 4 + 2][arow] = a4.z;
        As[akq * 4 + 3][arow] = a4.w;
        *(float4*)&Bs[brow][bfq * 4] =
            *(const float4*)(B + (long)(k0 + brow) * FF + f0 + bfq * 4);
        __syncthreads();
#pragma unroll
        for (int kk = 0; kk < 16; kk++) {
            float4 av = *(float4*)&As[kk][ty * 4];
            float4 bv = *(float4*)&Bs[kk][tx * 4];
            float ar[4] = {av.x, av.y, av.z, av.w};
            float br[4] = {bv.x, bv.y, bv.z, bv.w};
#pragma unroll
            for (int i = 0; i < 4; i++)
#pragma unroll
                for (int j = 0; j < 4; j++)
                    acc[i][j] = fmaf(ar[i], br[j], acc[i][j]);
        }
        __syncthreads();
    }

#pragma unroll
    for (int i = 0; i < 4; i++) {
        int row = m0 + ty * 4 + i;
        int col = f0 + tx * 4;
        float4 bv = *(const float4*)(bi + col);
        float4 o;
        o.x = acc[i][0] + bv.x; o.y = acc[i][1] + bv.y;
        o.z = acc[i][2] + bv.z; o.w = acc[i][3] + bv.w;
        if (MODE == 1) {
            float4 ev = *(const float4*)(g_e + (long)row * FF + col);
            o.x += ev.x; o.y += ev.y; o.z += ev.z; o.w += ev.w;
        }
        *(float4*)(C + (long)row * FF + col) = o;
    }
}

// ============================================================
// wu[h,d] = sum_f W[h,d,f]*u[h,f]   (and wv with v)
// one warp per (h,d)
// ============================================================
__global__ __launch_bounds__(256) void wuwv_kernel(
    const float* __restrict__ Wm, const float* __restrict__ u,
    const float* __restrict__ v)
{
    int w = blockIdx.x * 8 + (threadIdx.x >> 5);
    int lane = threadIdx.x & 31;
    int h = w / DD, d = w % DD;
    const float4* Wr = (const float4*)(Wm + ((long)h * DD + d) * FF);
    const float4* up = (const float4*)(u + (long)h * FF);
    const float4* vp = (const float4*)(v + (long)h * FF);
    float su = 0.f, sv = 0.f;
    for (int i = lane; i < FF / 4; i += 32) {
        float4 w4 = Wr[i], u4 = up[i], v4 = vp[i];
        su += w4.x * u4.x + w4.y * u4.y + w4.z * u4.z + w4.w * u4.w;
        sv += w4.x * v4.x + w4.y * v4.y + w4.z * v4.z + w4.w * v4.w;
    }
    su = warp_sum(su);
    sv = warp_sum(sv);
    if (lane == 0) {
        g_wu[h * DD + d] = su;
        g_wv[h * DD + d] = sv;
    }
}

// bu[h] = b[h].u[h], bv[h] = b[h].v[h] — one warp per head
__global__ void bubv_kernel(const float* __restrict__ b,
                            const float* __restrict__ u,
                            const float* __restrict__ v)
{
    int h = threadIdx.x >> 5;
    int lane = threadIdx.x & 31;
    float su = 0.f, sv = 0.f;
    for (int i = lane; i < FF; i += 32) {
        float bb = b[h * FF + i];
        su += bb * u[h * FF + i];
        sv += bb * v[h * FF + i];
    }
    su = warp_sum(su);
    sv = warp_sum(sv);
    if (lane == 0) { g_bu[h] = su; g_bv[h] = sv; }
}

// s[h,n] = nodes[n].wu[h] + bu[h] ; t similarly. one warp per (h,n)
__global__ __launch_bounds__(256) void st_kernel(const float* __restrict__ nodes)
{
    int w = blockIdx.x * 8 + (threadIdx.x >> 5);
    int lane = threadIdx.x & 31;
    int h = w >> 12;          // NN = 4096 = 2^12
    int n = w & (NN - 1);
    const float4* nr = (const float4*)(nodes + (long)n * DD);
    const float4* wu = (const float4*)(g_wu + (long)h * DD);
    const float4* wv = (const float4*)(g_wv + (long)h * DD);
    float ss = 0.f, tt = 0.f;
    for (int i = lane; i < DD / 4; i += 32) {
        float4 x = nr[i], a = wu[i], c = wv[i];
        ss += x.x * a.x + x.y * a.y + x.z * a.z + x.w * a.w;
        tt += x.x * c.x + x.y * c.y + x.z * c.z + x.w * c.w;
    }
    ss = warp_sum(ss);
    tt = warp_sum(tt);
    if (lane == 0) {
        g_s[h * NN + n] = ss + g_bu[h];
        g_t[h * NN + n] = tt + g_bv[h];
    }
}

// per head: hpmax = max_m leaky+(t_m), hmmin = min_m leaky-(t_m)
__global__ void minmax_kernel()
{
    int h = blockIdx.x;
    int tid = threadIdx.x;
    __shared__ float smx[256], smn[256];
    float mx = -1e30f, mn = 1e30f;
    for (int m = tid; m < NN; m += 256) {
        float t = g_t[h * NN + m];
        float hp = t >= 0.f ? t : ALPHA * t;
        float hm = t <= 0.f ? t : ALPHA * t;
        mx = fmaxf(mx, hp);
        mn = fminf(mn, hm);
    }
    smx[tid] = mx; smn[tid] = mn;
    __syncthreads();
    for (int sft = 128; sft > 0; sft >>= 1) {
        if (tid < sft) {
            smx[tid] = fmaxf(smx[tid], smx[tid + sft]);
            smn[tid] = fminf(smn[tid], smn[tid + sft]);
        }
        __syncthreads();
    }
    if (tid == 0) { g_hpmax[h] = smx[0]; g_hmmin[h] = smn[0]; }
}

// rmax[h,n] (O(1) via rank-1 structure) and invZ[h,n] = 1/sum_m exp(...)
__global__ __launch_bounds__(256) void z_kernel()
{
    int w = blockIdx.x * 8 + (threadIdx.x >> 5);
    int lane = threadIdx.x & 31;
    int h = w >> 12, n = w & (NN - 1);
    float s = g_s[h * NN + n];
    float rmax = s > 0.f ? s * g_hpmax[h] : (s < 0.f ? s * g_hmmin[h] : 0.f);
    const float* tp = g_t + (long)h * NN;
    float z = 0.f;
    for (int m = lane; m < NN; m += 32) {
        float sc = s * tp[m];
        sc = sc >= 0.f ? sc : ALPHA * sc;
        z += __expf(sc - rmax);
    }
    z = warp_sum(z);
    if (lane == 0) {
        g_rmax[h * NN + n] = rmax;
        g_invz[h * NN + n] = 1.f / z;
    }
}

// ============================================================
// Fused attention GEMM: out[n,f] = relu( (1/H) * sum_h invZ_n *
//      sum_m exp(leaky(s_n t_m) - rmax_n) * feats2[h,m,f] )
// A-tile regenerated on the fly (no N^2 traffic). 64x64 tile, BK=32.
// ============================================================
__global__ __launch_bounds__(256) void attn_kernel(float* __restrict__ out)
{
    __shared__ float As[32][64];
    __shared__ float Bs[32][64];
    __shared__ float s_sm[64], rmax_sm[64], invz_sm[64];
    __shared__ float t_sm[32];

    int tid = threadIdx.x;
    int n0 = blockIdx.y * 64, f0 = blockIdx.x * 64;
    int ty = tid >> 4, tx = tid & 15;
    int brow = tid >> 4, bfq = tid & 15;

    float outacc[4][4] = {};

    for (int h = 0; h < HH; h++) {
        if (tid < 64) {
            s_sm[tid]    = g_s[h * NN + n0 + tid];
            rmax_sm[tid] = g_rmax[h * NN + n0 + tid];
            invz_sm[tid] = g_invz[h * NN + n0 + tid];
        }
        float acc[4][4] = {};
        const float* fb = g_feats + (long)h * NN * FF;
        const float* tp = g_t + (long)h * NN;

        for (int m0 = 0; m0 < NN; m0 += 32) {
            __syncthreads();
            if (tid < 32) t_sm[tid] = tp[m0 + tid];
            __syncthreads();
            // generate w-tile: 2048 exps / 256 threads = 8 each
#pragma unroll
            for (int j = 0; j < 8; j++) {
                int idx = j * 256 + tid;
                int mm = idx >> 6, nn = idx & 63;
                float sv = s_sm[nn];
                float sc = sv * t_sm[mm];
                sc = sc >= 0.f ? sc : ALPHA * sc;
                As[mm][nn] = __expf(sc - rmax_sm[nn]);
            }
            // load feats2 tile 32x64
            *(float4*)&Bs[brow][bfq * 4] =
                *(const float4*)(fb + (long)(m0 + brow) * FF + f0 + bfq * 4);
            *(float4*)&Bs[brow + 16][bfq * 4] =
                *(const float4*)(fb + (long)(m0 + brow + 16) * FF + f0 + bfq * 4);
            __syncthreads();
#pragma unroll
            for (int kk = 0; kk < 32; kk++) {
                float4 av = *(float4*)&As[kk][ty * 4];
                float4 bv = *(float4*)&Bs[kk][tx * 4];
                float ar[4] = {av.x, av.y, av.z, av.w};
                float br[4] = {bv.x, bv.y, bv.z, bv.w};
#pragma unroll
                for (int i = 0; i < 4; i++)
#pragma unroll
                    for (int j = 0; j < 4; j++)
                        acc[i][j] = fmaf(ar[i], br[j], acc[i][j]);
            }
        }
        // flush head: scale by invZ (per row)
        float iz[4];
#pragma unroll
        for (int i = 0; i < 4; i++) iz[i] = invz_sm[ty * 4 + i];
#pragma unroll
        for (int i = 0; i < 4; i++)
#pragma unroll
            for (int j = 0; j < 4; j++)
                outacc[i][j] += iz[i] * acc[i][j];
        __syncthreads();   // protect s/rmax/invz smem before next head rewrites
    }

    const float invH = 1.0f / HH;
#pragma unroll
    for (int i = 0; i < 4; i++) {
        int row = n0 + ty * 4 + i;
        float4 o;
        o.x = fmaxf(outacc[i][0] * invH, 0.f);
        o.y = fmaxf(outacc[i][1] * invH, 0.f);
        o.z = fmaxf(outacc[i][2] * invH, 0.f);
        o.w = fmaxf(outacc[i][3] * invH, 0.f);
        *(float4*)(out + (long)row * FF + f0 + tx * 4) = o;
    }
}

extern "C" void kernel_launch(void* const* d_in, const int* in_sizes, int n_in,
                              void* d_out, int out_size)
{
    const float* nodes  = (const float*)d_in[0];
    const float* edges  = (const float*)d_in[1];
    const float* labels = (const float*)d_in[2];
    const float* We     = (const float*)d_in[3];
    const float* be     = (const float*)d_in[4];
    const float* Wm     = (const float*)d_in[5];
    const float* b      = (const float*)d_in[6];
    const float* u      = (const float*)d_in[7];
    const float* v      = (const float*)d_in[8];
    float* out = (float*)d_out;

    // e = (edges+labels)@We + be
    gemm64<0><<<dim3(FF / 64, NN / 64, 1), 256>>>(edges, labels, We, be);
    // rank-1 attention precomputation
    wuwv_kernel<<<HH * DD / 8, 256>>>(Wm, u, v);
    bubv_kernel<<<1, 128>>>(b, u, v);
    st_kernel<<<HH * NN / 8, 256>>>(nodes);
    minmax_kernel<<<HH, 256>>>();
    z_kernel<<<HH * NN / 8, 256>>>();
    // feats2[h] = nodes@W[h] + b[h] + e
    gemm64<1><<<dim3(FF / 64, NN / 64, HH), 256>>>(nodes, nullptr, Wm, b);
    // fused softmax(rank-1 scores) @ feats2, mean over heads, relu
    attn_kernel<<<dim3(FF / 64, NN / 64), 256>>>(out);
}

// round 3
// speedup vs baseline: 1.0013x; 1.0013x over previous
#include <cuda_runtime.h>

#define NN 4096
#define DD 512
#define FF 512
#define HH 4
#define ALPHA 0.3f

// ---- scratch (no allocation allowed; __device__ globals) ----
__device__ float g_e[NN * FF];            // 8 MB
__device__ float g_feats[HH * NN * FF];   // 32 MB (feats + e, per head)
__device__ float g_s[HH * NN];
__device__ float g_t[HH * NN];
__device__ float g_rmax[HH * NN];
__device__ float g_invz[HH * NN];
__device__ float g_wu[HH * DD];
__device__ float g_wv[HH * DD];
__device__ float g_bu[HH];
__device__ float g_bv[HH];
__device__ float g_hpmax[HH];
__device__ float g_hmmin[HH];

__device__ __forceinline__ float warp_sum(float x) {
#pragma unroll
    for (int o = 16; o > 0; o >>= 1) x += __shfl_xor_sync(0xffffffffu, x, o);
    return x;
}

// ============================================================
// Generic 64x64x16 fp32 GEMM.
// MODE 0:  g_e    = (A + A2) @ B  + bias          (e projection)
// MODE 1:  g_feats[h] = A @ B[h] + bias[h] + g_e  (per-head feats2)
// ============================================================
template <int MODE>
__global__ __launch_bounds__(256) void gemm64(
    const float* __restrict__ A, const float* __restrict__ A2,
    const float* __restrict__ Bm, const float* __restrict__ bias)
{
    const float* B;
    const float* bi;
    float* C;
    if (MODE == 0) {
        B = Bm; bi = bias; C = g_e;
    } else {
        int h = blockIdx.z;
        B = Bm + (long)h * DD * FF;
        bi = bias + (long)h * FF;
        C = g_feats + (long)h * NN * FF;
    }

    __shared__ float As[16][64];
    __shared__ float Bs[16][64];

    int tid = threadIdx.x;
    int m0 = blockIdx.y * 64, f0 = blockIdx.x * 64;
    int arow = tid >> 2, akq = tid & 3;     // A load: 64 rows x 4 float4
    int brow = tid >> 4, bfq = tid & 15;    // B load: 16 rows x 16 float4
    int ty = tid >> 4, tx = tid & 15;       // 16x16 threads, 4x4 microtile

    float acc[4][4] = {};

    for (int k0 = 0; k0 < DD; k0 += 16) {
        float4 a4 = *(const float4*)(A + (long)(m0 + arow) * DD + k0 + akq * 4);
        if (MODE == 0) {
            float4 c4 = *(const float4*)(A2 + (long)(m0 + arow) * DD + k0 + akq * 4);
            a4.x += c4.x; a4.y += c4.y; a4.z += c4.z; a4.w += c4.w;
        }
        As[akq * 4 + 0][arow] = a4.x;
        As[akq * 4 + 1][arow] = a4.y;
        As[akq * 4 + 2][arow] = a4.z;
        As[akq * 4 + 3][arow] = a4.w;
        *(float4*)&Bs[brow][bfq * 4] =
            *(const float4*)(B + (long)(k0 + brow) * FF + f0 + bfq * 4);
        __syncthreads();
#pragma unroll
        for (int kk = 0; kk < 16; kk++) {
            float4 av = *(float4*)&As[kk][ty * 4];
            float4 bv = *(float4*)&Bs[kk][tx * 4];
            float ar[4] = {av.x, av.y, av.z, av.w};
            float br[4] = {bv.x, bv.y, bv.z, bv.w};
#pragma unroll
            for (int i = 0; i < 4; i++)
#pragma unroll
                for (int j = 0; j < 4; j++)
                    acc[i][j] = fmaf(ar[i], br[j], acc[i][j]);
        }
        __syncthreads();
    }

#pragma unroll
    for (int i = 0; i < 4; i++) {
        int row = m0 + ty * 4 + i;
        int col = f0 + tx * 4;
        float4 bv = *(const float4*)(bi + col);
        float4 o;
        o.x = acc[i][0] + bv.x; o.y = acc[i][1] + bv.y;
        o.z = acc[i][2] + bv.z; o.w = acc[i][3] + bv.w;
        if (MODE == 1) {
            float4 ev = *(const float4*)(g_e + (long)row * FF + col);
            o.x += ev.x; o.y += ev.y; o.z += ev.z; o.w += ev.w;
        }
        *(float4*)(C + (long)row * FF + col) = o;
    }
}

// ============================================================
// wu[h,d] = sum_f W[h,d,f]*u[h,f]   (and wv with v)
// one warp per (h,d)
// ============================================================
__global__ __launch_bounds__(256) void wuwv_kernel(
    const float* __restrict__ Wm, const float* __restrict__ u,
    const float* __restrict__ v)
{
    int w = blockIdx.x * 8 + (threadIdx.x >> 5);
    int lane = threadIdx.x & 31;
    int h = w / DD, d = w % DD;
    const float4* Wr = (const float4*)(Wm + ((long)h * DD + d) * FF);
    const float4* up = (const float4*)(u + (long)h * FF);
    const float4* vp = (const float4*)(v + (long)h * FF);
    float su = 0.f, sv = 0.f;
    for (int i = lane; i < FF / 4; i += 32) {
        float4 w4 = Wr[i], u4 = up[i], v4 = vp[i];
        su += w4.x * u4.x + w4.y * u4.y + w4.z * u4.z + w4.w * u4.w;
        sv += w4.x * v4.x + w4.y * v4.y + w4.z * v4.z + w4.w * v4.w;
    }
    su = warp_sum(su);
    sv = warp_sum(sv);
    if (lane == 0) {
        g_wu[h * DD + d] = su;
        g_wv[h * DD + d] = sv;
    }
}

// bu[h] = b[h].u[h], bv[h] = b[h].v[h] — one warp per head
__global__ void bubv_kernel(const float* __restrict__ b,
                            const float* __restrict__ u,
                            const float* __restrict__ v)
{
    int h = threadIdx.x >> 5;
    int lane = threadIdx.x & 31;
    float su = 0.f, sv = 0.f;
    for (int i = lane; i < FF; i += 32) {
        float bb = b[h * FF + i];
        su += bb * u[h * FF + i];
        sv += bb * v[h * FF + i];
    }
    su = warp_sum(su);
    sv = warp_sum(sv);
    if (lane == 0) { g_bu[h] = su; g_bv[h] = sv; }
}

// s[h,n] = nodes[n].wu[h] + bu[h] ; t similarly. one warp per (h,n)
__global__ __launch_bounds__(256) void st_kernel(const float* __restrict__ nodes)
{
    int w = blockIdx.x * 8 + (threadIdx.x >> 5);
    int lane = threadIdx.x & 31;
    int h = w >> 12;          // NN = 4096 = 2^12
    int n = w & (NN - 1);
    const float4* nr = (const float4*)(nodes + (long)n * DD);
    const float4* wu = (const float4*)(g_wu + (long)h * DD);
    const float4* wv = (const float4*)(g_wv + (long)h * DD);
    float ss = 0.f, tt = 0.f;
    for (int i = lane; i < DD / 4; i += 32) {
        float4 x = nr[i], a = wu[i], c = wv[i];
        ss += x.x * a.x + x.y * a.y + x.z * a.z + x.w * a.w;
        tt += x.x * c.x + x.y * c.y + x.z * c.z + x.w * c.w;
    }
    ss = warp_sum(ss);
    tt = warp_sum(tt);
    if (lane == 0) {
        g_s[h * NN + n] = ss + g_bu[h];
        g_t[h * NN + n] = tt + g_bv[h];
    }
}

// per head: hpmax = max_m leaky+(t_m), hmmin = min_m leaky-(t_m)
__global__ void minmax_kernel()
{
    int h = blockIdx.x;
    int tid = threadIdx.x;
    __shared__ float smx[256], smn[256];
    float mx = -1e30f, mn = 1e30f;
    for (int m = tid; m < NN; m += 256) {
        float t = g_t[h * NN + m];
        float hp = t >= 0.f ? t : ALPHA * t;
        float hm = t <= 0.f ? t : ALPHA * t;
        mx = fmaxf(mx, hp);
        mn = fminf(mn, hm);
    }
    smx[tid] = mx; smn[tid] = mn;
    __syncthreads();
    for (int sft = 128; sft > 0; sft >>= 1) {
        if (tid < sft) {
            smx[tid] = fmaxf(smx[tid], smx[tid + sft]);
            smn[tid] = fminf(smn[tid], smn[tid + sft]);
        }
        __syncthreads();
    }
    if (tid == 0) { g_hpmax[h] = smx[0]; g_hmmin[h] = smn[0]; }
}

// rmax[h,n] (O(1) via rank-1 structure) and invZ[h,n] = 1/sum_m exp(...)
__global__ __launch_bounds__(256) void z_kernel()
{
    int w = blockIdx.x * 8 + (threadIdx.x >> 5);
    int lane = threadIdx.x & 31;
    int h = w >> 12, n = w & (NN - 1);
    float s = g_s[h * NN + n];
    float rmax = s > 0.f ? s * g_hpmax[h] : (s < 0.f ? s * g_hmmin[h] : 0.f);
    const float* tp = g_t + (long)h * NN;
    float z = 0.f;
    for (int m = lane; m < NN; m += 32) {
        float sc = s * tp[m];
        sc = sc >= 0.f ? sc : ALPHA * sc;
        z += __expf(sc - rmax);
    }
    z = warp_sum(z);
    if (lane == 0) {
        g_rmax[h * NN + n] = rmax;
        g_invz[h * NN + n] = 1.f / z;
    }
}

// ============================================================
// Fused attention GEMM: out[n,f] = relu( (1/H) * sum_h invZ_n *
//      sum_m exp(leaky(s_n t_m) - rmax_n) * feats2[h,m,f] )
// A-tile regenerated on the fly (no N^2 traffic). 64x64 tile, BK=32.
// ============================================================
__global__ __launch_bounds__(256) void attn_kernel(float* __restrict__ out)
{
    __shared__ float As[32][64];
    __shared__ float Bs[32][64];
    __shared__ float s_sm[64], rmax_sm[64], invz_sm[64];
    __shared__ float t_sm[32];

    int tid = threadIdx.x;
    int n0 = blockIdx.y * 64, f0 = blockIdx.x * 64;
    int ty = tid >> 4, tx = tid & 15;
    int brow = tid >> 4, bfq = tid & 15;

    float outacc[4][4] = {};

    for (int h = 0; h < HH; h++) {
        if (tid < 64) {
            s_sm[tid]    = g_s[h * NN + n0 + tid];
            rmax_sm[tid] = g_rmax[h * NN + n0 + tid];
            invz_sm[tid] = g_invz[h * NN + n0 + tid];
        }
        float acc[4][4] = {};
        const float* fb = g_feats + (long)h * NN * FF;
        const float* tp = g_t + (long)h * NN;

        for (int m0 = 0; m0 < NN; m0 += 32) {
            __syncthreads();
            if (tid < 32) t_sm[tid] = tp[m0 + tid];
            __syncthreads();
            // generate w-tile: 2048 exps / 256 threads = 8 each
#pragma unroll
            for (int j = 0; j < 8; j++) {
                int idx = j * 256 + tid;
                int mm = idx >> 6, nn = idx & 63;
                float sv = s_sm[nn];
                float sc = sv * t_sm[mm];
                sc = sc >= 0.f ? sc : ALPHA * sc;
                As[mm][nn] = __expf(sc - rmax_sm[nn]);
            }
            // load feats2 tile 32x64
            *(float4*)&Bs[brow][bfq * 4] =
                *(const float4*)(fb + (long)(m0 + brow) * FF + f0 + bfq * 4);
            *(float4*)&Bs[brow + 16][bfq * 4] =
                *(const float4*)(fb + (long)(m0 + brow + 16) * FF + f0 + bfq * 4);
            __syncthreads();
#pragma unroll
            for (int kk = 0; kk < 32; kk++) {
                float4 av = *(float4*)&As[kk][ty * 4];
                float4 bv = *(float4*)&Bs[kk][tx * 4];
                float ar[4] = {av.x, av.y, av.z, av.w};
                float br[4] = {bv.x, bv.y, bv.z, bv.w};
#pragma unroll
                for (int i = 0; i < 4; i++)
#pragma unroll
                    for (int j = 0; j < 4; j++)
                        acc[i][j] = fmaf(ar[i], br[j], acc[i][j]);
            }
        }
        // flush head: scale by invZ (per row)
        float iz[4];
#pragma unroll
        for (int i = 0; i < 4; i++) iz[i] = invz_sm[ty * 4 + i];
#pragma unroll
        for (int i = 0; i < 4; i++)
#pragma unroll
            for (int j = 0; j < 4; j++)
                outacc[i][j] += iz[i] * acc[i][j];
        __syncthreads();   // protect s/rmax/invz smem before next head rewrites
    }

    const float invH = 1.0f / HH;
#pragma unroll
    for (int i = 0; i < 4; i++) {
        int row = n0 + ty * 4 + i;
        float4 o;
        o.x = fmaxf(outacc[i][0] * invH, 0.f);
        o.y = fmaxf(outacc[i][1] * invH, 0.f);
        o.z = fmaxf(outacc[i][2] * invH, 0.f);
        o.w = fmaxf(outacc[i][3] * invH, 0.f);
        *(float4*)(out + (long)row * FF + f0 + tx * 4) = o;
    }
}

extern "C" void kernel_launch(void* const* d_in, const int* in_sizes, int n_in,
                              void* d_out, int out_size)
{
    const float* nodes  = (const float*)d_in[0];
    const float* edges  = (const float*)d_in[1];
    const float* labels = (const float*)d_in[2];
    const float* We     = (const float*)d_in[3];
    const float* be     = (const float*)d_in[4];
    const float* Wm     = (const float*)d_in[5];
    const float* b      = (const float*)d_in[6];
    const float* u      = (const float*)d_in[7];
    const float* v      = (const float*)d_in[8];
    float* out = (float*)d_out;

    // e = (edges+labels)@We + be
    gemm64<0><<<dim3(FF / 64, NN / 64, 1), 256>>>(edges, labels, We, be);
    // rank-1 attention precomputation
    wuwv_kernel<<<HH * DD / 8, 256>>>(Wm, u, v);
    bubv_kernel<<<1, 128>>>(b, u, v);
    st_kernel<<<HH * NN / 8, 256>>>(nodes);
    minmax_kernel<<<HH, 256>>>();
    z_kernel<<<HH * NN / 8, 256>>>();
    // feats2[h] = nodes@W[h] + b[h] + e
    gemm64<1><<<dim3(FF / 64, NN / 64, HH), 256>>>(nodes, nullptr, Wm, b);
    // fused softmax(rank-1 scores) @ feats2, mean over heads, relu
    attn_kernel<<<dim3(FF / 64, NN / 64), 256>>>(out);
}

// round 5
// speedup vs baseline: 2.4461x; 2.4430x over previous
#include <cuda_runtime.h>
#include <cstdint>

#define NN 4096
#define DD 512
#define FF 512
#define HH 4
#define KK 1024
#define ALPHA 0.3f

// ---- scratch (device globals; no allocation allowed) ----
__device__ float g_A[NN * KK];          // tf32-rounded [nodes | edges+labels], [m][k]
__device__ float g_BT[HH * FF * KK];    // tf32-rounded [h][f][k] = [W^T | We^T]
__device__ float g_bias2[HH * FF];
__device__ float g_featsT[(size_t)HH * FF * NN];  // [h][f][m], tf32-rounded
__device__ float g_s[HH * NN];
__device__ float g_t[HH * NN];
__device__ float g_rmax[HH * NN];
__device__ float g_invz[HH * NN];
__device__ float g_wu[HH * DD];
__device__ float g_wv[HH * DD];
__device__ float g_bu[HH];
__device__ float g_bv[HH];
__device__ float g_hpmax[HH];
__device__ float g_hmmin[HH];

// ================= helpers =================
__device__ __forceinline__ float warp_sum(float x) {
#pragma unroll
    for (int o = 16; o > 0; o >>= 1) x += __shfl_xor_sync(0xffffffffu, x, o);
    return x;
}
__device__ __forceinline__ uint32_t cvt_tf32(float x) {
    uint32_t r; asm("cvt.rna.tf32.f32 %0, %1;" : "=r"(r) : "f"(x)); return r;
}
__device__ __forceinline__ float tf32r(float x) {
    return __uint_as_float(cvt_tf32(x));
}
// fast exp on the FMA pipe: 2^(x*log2e), deg-4 Taylor on [-0.5,0.5], rel err ~4e-5.
// Used identically in z_kernel and weight gen so softmax normalization is consistent.
__device__ __forceinline__ float fexp(float x) {
    float y = fmaxf(x * 1.4426950408889634f, -100.0f);
    int   i = __float2int_rn(y);
    float f = y - (float)i;
    float p = 1.0f + f * (0.69314718056f + f * (0.2402265069f +
              f * (0.0555041087f + f * 0.00961812911f)));
    return __int_as_float((i + 127) << 23) * p;
}
__device__ __forceinline__ uint32_t smem_u32(const void* p) {
    uint32_t a;
    asm("{ .reg .u64 t; cvta.to.shared.u64 t, %1; cvt.u32.u64 %0, t; }"
        : "=r"(a) : "l"(p));
    return a;
}
__device__ __forceinline__ void cpasync16(uint32_t dst, const void* src) {
    asm volatile("cp.async.cg.shared.global [%0], [%1], 16;" :: "r"(dst), "l"(src));
}
__device__ __forceinline__ void cp_commit() {
    asm volatile("cp.async.commit_group;" ::: "memory");
}
template <int N>
__device__ __forceinline__ void cp_wait() {
    asm volatile("cp.async.wait_group %0;" :: "n"(N) : "memory");
}
// mma.sync m16n8k8 tf32 (legacy tensor-core path; compiles for compute_103)
__device__ __forceinline__ void mma1688(float* c, const uint32_t* a, uint32_t b0, uint32_t b1) {
    asm volatile(
        "mma.sync.aligned.m16n8k8.row.col.f32.tf32.tf32.f32 "
        "{%0,%1,%2,%3}, {%4,%5,%6,%7}, {%8,%9}, {%0,%1,%2,%3};"
        : "+f"(c[0]), "+f"(c[1]), "+f"(c[2]), "+f"(c[3])
        : "r"(a[0]), "r"(a[1]), "r"(a[2]), "r"(a[3]), "r"(b0), "r"(b1));
}

// ================= setup kernels =================
__global__ __launch_bounds__(256) void build_A(const float* __restrict__ nodes,
                                               const float* __restrict__ edges,
                                               const float* __restrict__ labels) {
    int i = blockIdx.x * 256 + threadIdx.x;   // float4 index over NN*DD
    int m = i >> 7;
    int dq = i & 127;
    float4 a = ((const float4*)nodes)[i];
    float4 x = ((const float4*)edges)[i];
    float4 y = ((const float4*)labels)[i];
    float* h0 = g_A + (size_t)m * KK + dq * 4;
    float av[4] = {a.x, a.y, a.z, a.w};
    float cv[4] = {x.x + y.x, x.y + y.y, x.z + y.z, x.w + y.w};
#pragma unroll
    for (int j = 0; j < 4; j++) {
        h0[j] = tf32r(av[j]);
        h0[DD + j] = tf32r(cv[j]);
    }
}

__global__ __launch_bounds__(256) void build_BT(const float* __restrict__ W,
                                                const float* __restrict__ We) {
    int e = blockIdx.x * 256 + threadIdx.x;   // over HH*FF*KK
    int h = e >> 19;
    int r = e & ((1 << 19) - 1);
    int f = r >> 10, k = r & 1023;
    float v = (k < DD) ? W[((size_t)h * DD + k) * FF + f]
                       : We[(size_t)(k - DD) * FF + f];
    g_BT[e] = tf32r(v);
}

__global__ void build_bias2(const float* __restrict__ b, const float* __restrict__ be) {
    int i = blockIdx.x * 256 + threadIdx.x;
    int f = i & (FF - 1);
    g_bias2[i] = b[i] + be[f];
}

// ================= rank-1 attention precomputation =================
__global__ __launch_bounds__(256) void wuwv_kernel(
    const float* __restrict__ Wm, const float* __restrict__ u, const float* __restrict__ v) {
    int w = blockIdx.x * 8 + (threadIdx.x >> 5);
    int lane = threadIdx.x & 31;
    int h = w / DD, d = w % DD;
    const float4* Wr = (const float4*)(Wm + ((long)h * DD + d) * FF);
    const float4* up = (const float4*)(u + (long)h * FF);
    const float4* vp = (const float4*)(v + (long)h * FF);
    float su = 0.f, sv = 0.f;
    for (int i = lane; i < FF / 4; i += 32) {
        float4 w4 = Wr[i], u4 = up[i], v4 = vp[i];
        su += w4.x * u4.x + w4.y * u4.y + w4.z * u4.z + w4.w * u4.w;
        sv += w4.x * v4.x + w4.y * v4.y + w4.z * v4.z + w4.w * v4.w;
    }
    su = warp_sum(su); sv = warp_sum(sv);
    if (lane == 0) { g_wu[h * DD + d] = su; g_wv[h * DD + d] = sv; }
}

__global__ void bubv_kernel(const float* __restrict__ b, const float* __restrict__ u,
                            const float* __restrict__ v) {
    int h = threadIdx.x >> 5;
    int lane = threadIdx.x & 31;
    float su = 0.f, sv = 0.f;
    for (int i = lane; i < FF; i += 32) {
        float bb = b[h * FF + i];
        su += bb * u[h * FF + i];
        sv += bb * v[h * FF + i];
    }
    su = warp_sum(su); sv = warp_sum(sv);
    if (lane == 0) { g_bu[h] = su; g_bv[h] = sv; }
}

__global__ __launch_bounds__(256) void st_kernel(const float* __restrict__ nodes) {
    int w = blockIdx.x * 8 + (threadIdx.x >> 5);
    int lane = threadIdx.x & 31;
    int h = w >> 12;
    int n = w & (NN - 1);
    const float4* nr = (const float4*)(nodes + (long)n * DD);
    const float4* wu = (const float4*)(g_wu + (long)h * DD);
    const float4* wv = (const float4*)(g_wv + (long)h * DD);
    float ss = 0.f, tt = 0.f;
    for (int i = lane; i < DD / 4; i += 32) {
        float4 x = nr[i], a = wu[i], c = wv[i];
        ss += x.x * a.x + x.y * a.y + x.z * a.z + x.w * a.w;
        tt += x.x * c.x + x.y * c.y + x.z * c.z + x.w * c.w;
    }
    ss = warp_sum(ss); tt = warp_sum(tt);
    if (lane == 0) {
        g_s[h * NN + n] = ss + g_bu[h];
        g_t[h * NN + n] = tt + g_bv[h];
    }
}

__global__ void minmax_kernel() {
    int h = blockIdx.x;
    int tid = threadIdx.x;
    __shared__ float smx[256], smn[256];
    float mx = -1e30f, mn = 1e30f;
    for (int m = tid; m < NN; m += 256) {
        float t = g_t[h * NN + m];
        float hp = t >= 0.f ? t : ALPHA * t;
        float hm = t <= 0.f ? t : ALPHA * t;
        mx = fmaxf(mx, hp);
        mn = fminf(mn, hm);
    }
    smx[tid] = mx; smn[tid] = mn;
    __syncthreads();
    for (int sft = 128; sft > 0; sft >>= 1) {
        if (tid < sft) {
            smx[tid] = fmaxf(smx[tid], smx[tid + sft]);
            smn[tid] = fminf(smn[tid], smn[tid + sft]);
        }
        __syncthreads();
    }
    if (tid == 0) { g_hpmax[h] = smx[0]; g_hmmin[h] = smn[0]; }
}

__global__ __launch_bounds__(256) void z_kernel() {
    int w = blockIdx.x * 8 + (threadIdx.x >> 5);
    int lane = threadIdx.x & 31;
    int h = w >> 12, n = w & (NN - 1);
    float s = g_s[h * NN + n];
    float rmax = s > 0.f ? s * g_hpmax[h] : (s < 0.f ? s * g_hmmin[h] : 0.f);
    const float* tp = g_t + (long)h * NN;
    float z = 0.f;
    for (int m = lane; m < NN; m += 32) {
        float sc = s * tp[m];
        sc = sc >= 0.f ? sc : ALPHA * sc;
        z += fexp(sc - rmax);
    }
    z = warp_sum(z);
    if (lane == 0) {
        g_rmax[h * NN + n] = rmax;
        g_invz[h * NN + n] = 1.f / z;
    }
}

// ================= feats GEMM (mma.sync tf32) =================
// featsT[h][f][m] = tf32( A'[m,:] . BT[h][f,:] + bias2[h][f] )
// CTA tile 128m x 128f, K-chunk 32, 8 warps (4x2), warp tile 32m x 64f.
#define F_AS 4608                  // 128*36 floats
#define F_STG 9216                 // As + Bs
#define F_SMEM (2 * F_STG * 4)     // bytes = 73728

__global__ __launch_bounds__(256) void feats_gemm() {
    extern __shared__ float sm[];
    int tid = threadIdx.x, wid = tid >> 5, lane = tid & 31;
    int g = lane >> 2, tg = lane & 3;
    int h = blockIdx.z;
    int m0 = blockIdx.y * 128, f0 = blockIdx.x * 128;
    const float* Bp = g_BT + (size_t)h * FF * KK;
    int warp_m = wid & 3, warp_n = wid >> 2;

    float acc[2][8][4];
#pragma unroll
    for (int a = 0; a < 2; a++)
#pragma unroll
        for (int b = 0; b < 8; b++)
#pragma unroll
            for (int c = 0; c < 4; c++) acc[a][b][c] = 0.f;

    int prow = tid & 127, pseg = tid >> 7;   // copy mapping

    auto prod = [&](int c, int s) {
        float* As = sm + s * F_STG;
        float* Bs = As + F_AS;
        int k0 = c * 32;
        const float* asrc = g_A + (size_t)(m0 + prow) * KK + k0 + pseg * 16;
        const float* bsrc = Bp + (size_t)(f0 + prow) * KK + k0 + pseg * 16;
        uint32_t ad = smem_u32(As + prow * 36 + pseg * 16);
        uint32_t bd = smem_u32(Bs + prow * 36 + pseg * 16);
#pragma unroll
        for (int j = 0; j < 4; j++) {
            cpasync16(ad + j * 16, asrc + j * 4);
            cpasync16(bd + j * 16, bsrc + j * 4);
        }
    };
    auto domma = [&](int s) {
        float* As = sm + s * F_STG;
        float* Bs = As + F_AS;
#pragma unroll
        for (int ks = 0; ks < 4; ks++) {
            uint32_t a[2][4];
#pragma unroll
            for (int mt = 0; mt < 2; mt++) {
                int base = warp_m * 32 + mt * 16;
                a[mt][0] = __float_as_uint(As[(base + g) * 36 + ks * 8 + tg]);
                a[mt][1] = __float_as_uint(As[(base + 8 + g) * 36 + ks * 8 + tg]);
                a[mt][2] = __float_as_uint(As[(base + g) * 36 + ks * 8 + tg + 4]);
                a[mt][3] = __float_as_uint(As[(base + 8 + g) * 36 + ks * 8 + tg + 4]);
            }
#pragma unroll
            for (int nt = 0; nt < 8; nt++) {
                int fc = warp_n * 64 + nt * 8 + g;
                uint32_t b0 = __float_as_uint(Bs[fc * 36 + ks * 8 + tg]);
                uint32_t b1 = __float_as_uint(Bs[fc * 36 + ks * 8 + tg + 4]);
                mma1688(acc[0][nt], a[0], b0, b1);
                mma1688(acc[1][nt], a[1], b0, b1);
            }
        }
    };

    const int NIT = KK / 32;   // 32
    prod(0, 0); cp_commit();
    for (int i = 0; i < NIT; i++) {
        int s = i & 1;
        if (i + 1 < NIT) { prod(i + 1, s ^ 1); cp_commit(); cp_wait<1>(); }
        else cp_wait<0>();
        __syncthreads();
        domma(s);
        __syncthreads();
    }

    float* dst = g_featsT + (size_t)h * FF * NN;
#pragma unroll
    for (int mt = 0; mt < 2; mt++) {
#pragma unroll
        for (int nt = 0; nt < 8; nt++) {
            int row = m0 + warp_m * 32 + mt * 16 + g;
            int col = f0 + warp_n * 64 + nt * 8 + tg * 2;
            float b0v = g_bias2[h * FF + col];
            float b1v = g_bias2[h * FF + col + 1];
            dst[(size_t)col * NN + row]           = tf32r(acc[mt][nt][0] + b0v);
            dst[(size_t)(col + 1) * NN + row]     = tf32r(acc[mt][nt][1] + b1v);
            dst[(size_t)col * NN + row + 8]       = tf32r(acc[mt][nt][2] + b0v);
            dst[(size_t)(col + 1) * NN + row + 8] = tf32r(acc[mt][nt][3] + b1v);
        }
    }
}

// ================= fused attention GEMM (mma.sync tf32) =================
// out[n][f] = relu(0.25 * sum_{h,m} w[h,n,m] * featsT[h][f][m]),
// w generated on the fly from rank-1 structure (zero N^2 traffic).
// CTA tile 64n x 128f, K-chunk 32, chunks over (h, m): 512 iters.
// 8 warps (2x4), warp tile 32n x 32f.
#define A_AS 2304                  // 64*36
#define A_BS 4608                  // 128*36
#define A_STG (A_AS + A_BS)        // 6912
#define A_SRIZ 768                 // 3 * 4h * 64n
#define A_SMEM ((A_SRIZ + 2 * A_STG) * 4)   // 58368 bytes

__global__ __launch_bounds__(256) void attn_gemm(float* __restrict__ out) {
    extern __shared__ float sm[];
    int tid = threadIdx.x, wid = tid >> 5, lane = tid & 31;
    int g = lane >> 2, tg = lane & 3;
    int n0 = blockIdx.y * 64, f0 = blockIdx.x * 128;
    int warp_m = wid & 1, warp_n = wid >> 1;

    // preload s/rmax/invz for all 4 heads (64 rows each)
    {
        int hh = tid >> 6, nl = tid & 63;     // 256 = 4*64
        sm[tid]       = g_s[hh * NN + n0 + nl];
        sm[256 + tid] = g_rmax[hh * NN + n0 + nl];
        sm[512 + tid] = g_invz[hh * NN + n0 + nl];
    }
    __syncthreads();

    float acc[2][4][4];
#pragma unroll
    for (int a = 0; a < 2; a++)
#pragma unroll
        for (int b = 0; b < 4; b++)
#pragma unroll
            for (int c = 0; c < 4; c++) acc[a][b][c] = 0.f;

    int nloc = tid & 63, kq = tid >> 6;       // weight gen mapping
    int prow = tid & 127, pseg = tid >> 7;    // B copy mapping

    auto prod = [&](int c, int s) {
        float* As = sm + A_SRIZ + s * A_STG;
        float* Bs = As + A_AS;
        int h = c >> 7;
        int m0 = (c & 127) << 5;
        // --- generate 8 weights into As[nloc][kq*8..+8) ---
        float sv = sm[h * 64 + nloc];
        float rm = sm[256 + h * 64 + nloc];
        float iz = sm[512 + h * 64 + nloc];
        const float* tp = g_t + h * NN + m0 + kq * 8;
        float w[8];
#pragma unroll
        for (int q = 0; q < 8; q++) {
            float t = __ldg(tp + q);
            float sc = sv * t;
            sc = sc >= 0.f ? sc : ALPHA * sc;
            w[q] = tf32r(iz * fexp(sc - rm));
        }
        float* d = As + nloc * 36 + kq * 8;
        *(float4*)d       = make_float4(w[0], w[1], w[2], w[3]);
        *(float4*)(d + 4) = make_float4(w[4], w[5], w[6], w[7]);
        // --- B tile: featsT[h][f0+row][m0 .. +32) ---
        const float* bsrc = g_featsT + (size_t)h * FF * NN
                          + (size_t)(f0 + prow) * NN + m0 + pseg * 16;
        uint32_t bd = smem_u32(Bs + prow * 36 + pseg * 16);
#pragma unroll
        for (int j = 0; j < 4; j++) cpasync16(bd + j * 16, bsrc + j * 4);
    };
    auto domma = [&](int s) {
        float* As = sm + A_SRIZ + s * A_STG;
        float* Bs = As + A_AS;
#pragma unroll
        for (int ks = 0; ks < 4; ks++) {
            uint32_t a[2][4];
#pragma unroll
            for (int mt = 0; mt < 2; mt++) {
                int base = warp_m * 32 + mt * 16;
                a[mt][0] = __float_as_uint(As[(base + g) * 36 + ks * 8 + tg]);
                a[mt][1] = __float_as_uint(As[(base + 8 + g) * 36 + ks * 8 + tg]);
                a[mt][2] = __float_as_uint(As[(base + g) * 36 + ks * 8 + tg + 4]);
                a[mt][3] = __float_as_uint(As[(base + 8 + g) * 36 + ks * 8 + tg + 4]);
            }
#pragma unroll
            for (int nt = 0; nt < 4; nt++) {
                int fc = warp_n * 32 + nt * 8 + g;
                uint32_t b0 = __float_as_uint(Bs[fc * 36 + ks * 8 + tg]);
                uint32_t b1 = __float_as_uint(Bs[fc * 36 + ks * 8 + tg + 4]);
                mma1688(acc[0][nt], a[0], b0, b1);
                mma1688(acc[1][nt], a[1], b0, b1);
            }
        }
    };

    const int NIT = HH * (NN / 32);   // 512
    prod(0, 0); cp_commit();
    for (int i = 0; i < NIT; i++) {
        int s = i & 1;
        if (i + 1 < NIT) { prod(i + 1, s ^ 1); cp_commit(); cp_wait<1>(); }
        else cp_wait<0>();
        __syncthreads();
        domma(s);
        __syncthreads();
    }

#pragma unroll
    for (int mt = 0; mt < 2; mt++) {
#pragma unroll
        for (int nt = 0; nt < 4; nt++) {
            int row = n0 + warp_m * 32 + mt * 16 + g;
            int col = f0 + warp_n * 32 + nt * 8 + tg * 2;
            float2 v0, v1;
            v0.x = fmaxf(0.25f * acc[mt][nt][0], 0.f);
            v0.y = fmaxf(0.25f * acc[mt][nt][1], 0.f);
            v1.x = fmaxf(0.25f * acc[mt][nt][2], 0.f);
            v1.y = fmaxf(0.25f * acc[mt][nt][3], 0.f);
            *(float2*)(out + (size_t)row * FF + col) = v0;
            *(float2*)(out + (size_t)(row + 8) * FF + col) = v1;
        }
    }
}

// ================= launch =================
extern "C" void kernel_launch(void* const* d_in, const int* in_sizes, int n_in,
                              void* d_out, int out_size)
{
    const float* nodes  = (const float*)d_in[0];
    const float* edges  = (const float*)d_in[1];
    const float* labels = (const float*)d_in[2];
    const float* We     = (const float*)d_in[3];
    const float* be     = (const float*)d_in[4];
    const float* Wm     = (const float*)d_in[5];
    const float* b      = (const float*)d_in[6];
    const float* u      = (const float*)d_in[7];
    const float* v      = (const float*)d_in[8];
    float* out = (float*)d_out;

    static bool attr_done = false;
    if (!attr_done) {
        cudaFuncSetAttribute(feats_gemm, cudaFuncAttributeMaxDynamicSharedMemorySize, F_SMEM);
        cudaFuncSetAttribute(attn_gemm, cudaFuncAttributeMaxDynamicSharedMemorySize, A_SMEM);
        attr_done = true;
    }

    build_A<<<NN * DD / 4 / 256, 256>>>(nodes, edges, labels);
    build_BT<<<HH * FF * KK / 256, 256>>>(Wm, We);
    build_bias2<<<HH * FF / 256, 256>>>(b, be);
    wuwv_kernel<<<HH * DD / 8, 256>>>(Wm, u, v);
    bubv_kernel<<<1, 128>>>(b, u, v);
    st_kernel<<<HH * NN / 8, 256>>>(nodes);
    minmax_kernel<<<HH, 256>>>();
    z_kernel<<<HH * NN / 8, 256>>>();
    feats_gemm<<<dim3(FF / 128, NN / 128, HH), 256, F_SMEM>>>();
    attn_gemm<<<dim3(FF / 128, NN / 64), 256, A_SMEM>>>(out);
}

// round 6
// speedup vs baseline: 2.4929x; 1.0191x over previous
#include <cuda_runtime.h>
#include <cstdint>

#define NN 4096
#define DD 512
#define FF 512
#define HH 4
#define KK 1024
#define ALPHA 0.3f
#define L2E 1.4426950408889634f

// ---- scratch (device globals; no allocation allowed) ----
__device__ float g_A[NN * KK];          // tf32-rounded [nodes | edges+labels], [m][k]
__device__ float g_BT[HH * FF * KK];    // tf32-rounded [h][f][k] = [W^T | We^T]
__device__ float g_bias2[HH * FF];
__device__ float g_featsT[(size_t)HH * FF * NN];  // [h][f][m], tf32-rounded
__device__ float g_s[HH * NN];
__device__ float g_t[HH * NN];
__device__ float g_rmax[HH * NN];
__device__ float g_invz[HH * NN];
__device__ float g_wu[HH * DD];
__device__ float g_wv[HH * DD];
__device__ float g_bu[HH];
__device__ float g_bv[HH];
__device__ float g_hpmax[HH];
__device__ float g_hmmin[HH];

// ================= helpers =================
__device__ __forceinline__ float warp_sum(float x) {
#pragma unroll
    for (int o = 16; o > 0; o >>= 1) x += __shfl_xor_sync(0xffffffffu, x, o);
    return x;
}
__device__ __forceinline__ uint32_t cvt_tf32(float x) {
    uint32_t r; asm("cvt.rna.tf32.f32 %0, %1;" : "=r"(r) : "f"(x)); return r;
}
__device__ __forceinline__ float tf32r(float x) {
    return __uint_as_float(cvt_tf32(x));
}
// fast exp on the FMA pipe (z_kernel); weight gen uses the same poly via exp2.
__device__ __forceinline__ float fexp(float x) {
    float y = fmaxf(x * L2E, -100.0f);
    int   i = __float2int_rn(y);
    float f = y - (float)i;
    float p = 1.0f + f * (0.69314718056f + f * (0.2402265069f +
              f * (0.0555041087f + f * 0.00961812911f)));
    return __int_as_float((i + 127) << 23) * p;
}
// 2^y with same poly, y pre-clamped
__device__ __forceinline__ float fexp2(float y) {
    int   i = __float2int_rn(y);
    float f = y - (float)i;
    float p = 1.0f + f * (0.69314718056f + f * (0.2402265069f +
              f * (0.0555041087f + f * 0.00961812911f)));
    return __int_as_float((i + 127) << 23) * p;
}
__device__ __forceinline__ uint32_t smem_u32(const void* p) {
    uint32_t a;
    asm("{ .reg .u64 t; cvta.to.shared.u64 t, %1; cvt.u32.u64 %0, t; }"
        : "=r"(a) : "l"(p));
    return a;
}
__device__ __forceinline__ void cpasync16(uint32_t dst, const void* src) {
    asm volatile("cp.async.cg.shared.global [%0], [%1], 16;" :: "r"(dst), "l"(src));
}
__device__ __forceinline__ void cp_commit() {
    asm volatile("cp.async.commit_group;" ::: "memory");
}
template <int N>
__device__ __forceinline__ void cp_wait() {
    asm volatile("cp.async.wait_group %0;" :: "n"(N) : "memory");
}
__device__ __forceinline__ void mma1688(float* c, const uint32_t* a, uint32_t b0, uint32_t b1) {
    asm volatile(
        "mma.sync.aligned.m16n8k8.row.col.f32.tf32.tf32.f32 "
        "{%0,%1,%2,%3}, {%4,%5,%6,%7}, {%8,%9}, {%0,%1,%2,%3};"
        : "+f"(c[0]), "+f"(c[1]), "+f"(c[2]), "+f"(c[3])
        : "r"(a[0]), "r"(a[1]), "r"(a[2]), "r"(a[3]), "r"(b0), "r"(b1));
}

// ================= setup kernels =================
__global__ __launch_bounds__(256) void build_A(const float* __restrict__ nodes,
                                               const float* __restrict__ edges,
                                               const float* __restrict__ labels) {
    int i = blockIdx.x * 256 + threadIdx.x;
    int m = i >> 7;
    int dq = i & 127;
    float4 a = ((const float4*)nodes)[i];
    float4 x = ((const float4*)edges)[i];
    float4 y = ((const float4*)labels)[i];
    float* h0 = g_A + (size_t)m * KK + dq * 4;
    float av[4] = {a.x, a.y, a.z, a.w};
    float cv[4] = {x.x + y.x, x.y + y.y, x.z + y.z, x.w + y.w};
#pragma unroll
    for (int j = 0; j < 4; j++) {
        h0[j] = tf32r(av[j]);
        h0[DD + j] = tf32r(cv[j]);
    }
}

// tiled transpose: g_BT[h][f][k] = tf32(W[h][k][f] or We[k-DD][f])
__global__ __launch_bounds__(256) void build_BT(const float* __restrict__ W,
                                                const float* __restrict__ We) {
    __shared__ float tile[32][33];
    int h = blockIdx.z;
    int k0 = blockIdx.x * 32, f0 = blockIdx.y * 32;
    int tx = threadIdx.x & 31, ty0 = threadIdx.x >> 5;   // 32 x 8
#pragma unroll
    for (int j = 0; j < 4; j++) {
        int ty = ty0 * 4 + j;
        int k = k0 + ty;
        float v = (k < DD) ? W[((size_t)h * DD + k) * FF + f0 + tx]
                           : We[(size_t)(k - DD) * FF + f0 + tx];
        tile[ty][tx] = v;
    }
    __syncthreads();
#pragma unroll
    for (int j = 0; j < 4; j++) {
        int ty = ty0 * 4 + j;
        g_BT[((size_t)h * FF + f0 + ty) * KK + k0 + tx] = tf32r(tile[tx][ty]);
    }
}

__global__ void build_bias2(const float* __restrict__ b, const float* __restrict__ be) {
    int i = blockIdx.x * 256 + threadIdx.x;
    int f = i & (FF - 1);
    g_bias2[i] = b[i] + be[f];
}

// ================= feats GEMM (mma.sync tf32) =================
#define F_AS 4608                  // 128*36 floats
#define F_STG 9216
#define F_SMEM (2 * F_STG * 4)

__global__ __launch_bounds__(256) void feats_gemm() {
    extern __shared__ float sm[];
    int tid = threadIdx.x, wid = tid >> 5, lane = tid & 31;
    int g = lane >> 2, tg = lane & 3;
    int h = blockIdx.z;
    int m0 = blockIdx.y * 128, f0 = blockIdx.x * 128;
    const float* Bp = g_BT + (size_t)h * FF * KK;
    int warp_m = wid & 3, warp_n = wid >> 2;

    float acc[2][8][4];
#pragma unroll
    for (int a = 0; a < 2; a++)
#pragma unroll
        for (int b = 0; b < 8; b++)
#pragma unroll
            for (int c = 0; c < 4; c++) acc[a][b][c] = 0.f;

    int prow = tid & 127, pseg = tid >> 7;

    auto prod = [&](int c, int s) {
        float* As = sm + s * F_STG;
        float* Bs = As + F_AS;
        int k0 = c * 32;
        const float* asrc = g_A + (size_t)(m0 + prow) * KK + k0 + pseg * 16;
        const float* bsrc = Bp + (size_t)(f0 + prow) * KK + k0 + pseg * 16;
        uint32_t ad = smem_u32(As + prow * 36 + pseg * 16);
        uint32_t bd = smem_u32(Bs + prow * 36 + pseg * 16);
#pragma unroll
        for (int j = 0; j < 4; j++) {
            cpasync16(ad + j * 16, asrc + j * 4);
            cpasync16(bd + j * 16, bsrc + j * 4);
        }
    };
    auto domma = [&](int s) {
        float* As = sm + s * F_STG;
        float* Bs = As + F_AS;
#pragma unroll
        for (int ks = 0; ks < 4; ks++) {
            uint32_t a[2][4];
#pragma unroll
            for (int mt = 0; mt < 2; mt++) {
                int base = warp_m * 32 + mt * 16;
                a[mt][0] = __float_as_uint(As[(base + g) * 36 + ks * 8 + tg]);
                a[mt][1] = __float_as_uint(As[(base + 8 + g) * 36 + ks * 8 + tg]);
                a[mt][2] = __float_as_uint(As[(base + g) * 36 + ks * 8 + tg + 4]);
                a[mt][3] = __float_as_uint(As[(base + 8 + g) * 36 + ks * 8 + tg + 4]);
            }
#pragma unroll
            for (int nt = 0; nt < 8; nt++) {
                int fc = warp_n * 64 + nt * 8 + g;
                uint32_t b0 = __float_as_uint(Bs[fc * 36 + ks * 8 + tg]);
                uint32_t b1 = __float_as_uint(Bs[fc * 36 + ks * 8 + tg + 4]);
                mma1688(acc[0][nt], a[0], b0, b1);
                mma1688(acc[1][nt], a[1], b0, b1);
            }
        }
    };

    const int NIT = KK / 32;
    prod(0, 0); cp_commit();
    for (int i = 0; i < NIT; i++) {
        int s = i & 1;
        if (i + 1 < NIT) { prod(i + 1, s ^ 1); cp_commit(); cp_wait<1>(); }
        else cp_wait<0>();
        __syncthreads();
        domma(s);
        __syncthreads();
    }

    float* dst = g_featsT + (size_t)h * FF * NN;
#pragma unroll
    for (int mt = 0; mt < 2; mt++) {
#pragma unroll
        for (int nt = 0; nt < 8; nt++) {
            int row = m0 + warp_m * 32 + mt * 16 + g;
            int col = f0 + warp_n * 64 + nt * 8 + tg * 2;
            float b0v = g_bias2[h * FF + col];
            float b1v = g_bias2[h * FF + col + 1];
            dst[(size_t)col * NN + row]           = tf32r(acc[mt][nt][0] + b0v);
            dst[(size_t)(col + 1) * NN + row]     = tf32r(acc[mt][nt][1] + b1v);
            dst[(size_t)col * NN + row + 8]       = tf32r(acc[mt][nt][2] + b0v);
            dst[(size_t)(col + 1) * NN + row + 8] = tf32r(acc[mt][nt][3] + b1v);
        }
    }
}

// ================= rank-1 attention precomputation =================
__global__ __launch_bounds__(256) void wuwv_kernel(
    const float* __restrict__ Wm, const float* __restrict__ u, const float* __restrict__ v) {
    int w = blockIdx.x * 8 + (threadIdx.x >> 5);
    int lane = threadIdx.x & 31;
    int h = w / DD, d = w % DD;
    const float4* Wr = (const float4*)(Wm + ((long)h * DD + d) * FF);
    const float4* up = (const float4*)(u + (long)h * FF);
    const float4* vp = (const float4*)(v + (long)h * FF);
    float su = 0.f, sv = 0.f;
    for (int i = lane; i < FF / 4; i += 32) {
        float4 w4 = Wr[i], u4 = up[i], v4 = vp[i];
        su += w4.x * u4.x + w4.y * u4.y + w4.z * u4.z + w4.w * u4.w;
        sv += w4.x * v4.x + w4.y * v4.y + w4.z * v4.z + w4.w * v4.w;
    }
    su = warp_sum(su); sv = warp_sum(sv);
    if (lane == 0) { g_wu[h * DD + d] = su; g_wv[h * DD + d] = sv; }
}

__global__ void bubv_kernel(const float* __restrict__ b, const float* __restrict__ u,
                            const float* __restrict__ v) {
    int h = threadIdx.x >> 5;
    int lane = threadIdx.x & 31;
    float su = 0.f, sv = 0.f;
    for (int i = lane; i < FF; i += 32) {
        float bb = b[h * FF + i];
        su += bb * u[h * FF + i];
        sv += bb * v[h * FF + i];
    }
    su = warp_sum(su); sv = warp_sum(sv);
    if (lane == 0) { g_bu[h] = su; g_bv[h] = sv; }
}

__global__ __launch_bounds__(256) void st_kernel(const float* __restrict__ nodes) {
    int w = blockIdx.x * 8 + (threadIdx.x >> 5);
    int lane = threadIdx.x & 31;
    int h = w >> 12;
    int n = w & (NN - 1);
    const float4* nr = (const float4*)(nodes + (long)n * DD);
    const float4* wu = (const float4*)(g_wu + (long)h * DD);
    const float4* wv = (const float4*)(g_wv + (long)h * DD);
    float ss = 0.f, tt = 0.f;
    for (int i = lane; i < DD / 4; i += 32) {
        float4 x = nr[i], a = wu[i], c = wv[i];
        ss += x.x * a.x + x.y * a.y + x.z * a.z + x.w * a.w;
        tt += x.x * c.x + x.y * c.y + x.z * c.z + x.w * c.w;
    }
    ss = warp_sum(ss); tt = warp_sum(tt);
    if (lane == 0) {
        g_s[h * NN + n] = ss + g_bu[h];
        g_t[h * NN + n] = tt + g_bv[h];
    }
}

__global__ void minmax_kernel() {
    int h = blockIdx.x;
    int tid = threadIdx.x;
    __shared__ float smx[256], smn[256];
    float mx = -1e30f, mn = 1e30f;
    for (int m = tid; m < NN; m += 256) {
        float t = g_t[h * NN + m];
        float hp = t >= 0.f ? t : ALPHA * t;
        float hm = t <= 0.f ? t : ALPHA * t;
        mx = fmaxf(mx, hp);
        mn = fminf(mn, hm);
    }
    smx[tid] = mx; smn[tid] = mn;
    __syncthreads();
    for (int sft = 128; sft > 0; sft >>= 1) {
        if (tid < sft) {
            smx[tid] = fmaxf(smx[tid], smx[tid + sft]);
            smn[tid] = fminf(smn[tid], smn[tid + sft]);
        }
        __syncthreads();
    }
    if (tid == 0) { g_hpmax[h] = smx[0]; g_hmmin[h] = smn[0]; }
}

__global__ __launch_bounds__(256) void z_kernel() {
    int w = blockIdx.x * 8 + (threadIdx.x >> 5);
    int lane = threadIdx.x & 31;
    int h = w >> 12, n = w & (NN - 1);
    float s = g_s[h * NN + n];
    float rmax = s > 0.f ? s * g_hpmax[h] : (s < 0.f ? s * g_hmmin[h] : 0.f);
    const float* tp = g_t + (long)h * NN;
    float z = 0.f;
    for (int m = lane; m < NN; m += 32) {
        float sc = s * tp[m];
        sc = sc >= 0.f ? sc : ALPHA * sc;
        z += fexp(sc - rmax);
    }
    z = warp_sum(z);
    if (lane == 0) {
        g_rmax[h * NN + n] = rmax;
        g_invz[h * NN + n] = 1.f / z;
    }
}

// ================= fused attention GEMM (mma.sync tf32) =================
// CTA tile 128n x 128f (single wave: grid 4x32=128), 8 warps (4m x 2n grid),
// warp tile 32n x 64f. K-chunks of 32 over (h, m): 512 iters.
// Weight: w = 2^( s_n*t_m * (sc>=0 ? L2E : 0.3*L2E) + C_n ),
//   C_n = log2(invz_n) - rmax_n*L2E  (folds softmax scale + row max).
#define A_CONST 1024               // s_sm[512] + c_sm[512]
#define A_AS 4608                  // 128*36
#define A_STG 9216                 // As + Bs
#define A_SMEM ((A_CONST + 2 * A_STG) * 4)   // 77824 bytes

__global__ __launch_bounds__(256) void attn_gemm(float* __restrict__ out) {
    extern __shared__ float sm[];
    float* s_sm = sm;              // [4h][128]
    float* c_sm = sm + 512;        // [4h][128]
    int tid = threadIdx.x, wid = tid >> 5, lane = tid & 31;
    int g = lane >> 2, tg = lane & 3;
    int n0 = blockIdx.y * 128, f0 = blockIdx.x * 128;
    int warp_m = wid & 3, warp_n = wid >> 2;

#pragma unroll
    for (int j = 0; j < 2; j++) {
        int idx = j * 256 + tid;
        int hh = idx >> 7, nl = idx & 127;
        float iz = g_invz[hh * NN + n0 + nl];
        float rm = g_rmax[hh * NN + n0 + nl];
        s_sm[idx] = g_s[hh * NN + n0 + nl];
        c_sm[idx] = __log2f(iz) - rm * L2E;
    }
    __syncthreads();

    float acc[2][8][4];
#pragma unroll
    for (int a = 0; a < 2; a++)
#pragma unroll
        for (int b = 0; b < 8; b++)
#pragma unroll
            for (int c = 0; c < 4; c++) acc[a][b][c] = 0.f;

    int nloc = tid & 127, kq = tid >> 7;      // weight gen: 16 k's each
    int prow = tid & 127, pseg = tid >> 7;    // B copy

    auto prod = [&](int c, int s) {
        float* As = sm + A_CONST + s * A_STG;
        float* Bs = As + A_AS;
        int h = c >> 7;
        int m0 = (c & 127) << 5;
        float sv = s_sm[h * 128 + nloc];
        float cn = c_sm[h * 128 + nloc];
        const float4* tp = (const float4*)(g_t + h * NN + m0 + kq * 16);
        float w[16];
#pragma unroll
        for (int q = 0; q < 4; q++) {
            float4 t4 = __ldg(tp + q);
            float tv[4] = {t4.x, t4.y, t4.z, t4.w};
#pragma unroll
            for (int r = 0; r < 4; r++) {
                float sc = sv * tv[r];
                float mult = sc >= 0.f ? L2E : (ALPHA * L2E);
                float y = fmaxf(fmaf(sc, mult, cn), -126.f);
                w[q * 4 + r] = tf32r(fexp2(y));
            }
        }
        float* d = As + nloc * 36 + kq * 16;
        *(float4*)d        = make_float4(w[0], w[1], w[2], w[3]);
        *(float4*)(d + 4)  = make_float4(w[4], w[5], w[6], w[7]);
        *(float4*)(d + 8)  = make_float4(w[8], w[9], w[10], w[11]);
        *(float4*)(d + 12) = make_float4(w[12], w[13], w[14], w[15]);
        const float* bsrc = g_featsT + (size_t)h * FF * NN
                          + (size_t)(f0 + prow) * NN + m0 + pseg * 16;
        uint32_t bd = smem_u32(Bs + prow * 36 + pseg * 16);
#pragma unroll
        for (int j = 0; j < 4; j++) cpasync16(bd + j * 16, bsrc + j * 4);
    };
    auto domma = [&](int s) {
        float* As = sm + A_CONST + s * A_STG;
        float* Bs = As + A_AS;
#pragma unroll
        for (int ks = 0; ks < 4; ks++) {
            uint32_t a[2][4];
#pragma unroll
            for (int mt = 0; mt < 2; mt++) {
                int base = warp_m * 32 + mt * 16;
                a[mt][0] = __float_as_uint(As[(base + g) * 36 + ks * 8 + tg]);
                a[mt][1] = __float_as_uint(As[(base + 8 + g) * 36 + ks * 8 + tg]);
                a[mt][2] = __float_as_uint(As[(base + g) * 36 + ks * 8 + tg + 4]);
                a[mt][3] = __float_as_uint(As[(base + 8 + g) * 36 + ks * 8 + tg + 4]);
            }
#pragma unroll
            for (int nt = 0; nt < 8; nt++) {
                int fc = warp_n * 64 + nt * 8 + g;
                uint32_t b0 = __float_as_uint(Bs[fc * 36 + ks * 8 + tg]);
                uint32_t b1 = __float_as_uint(Bs[fc * 36 + ks * 8 + tg + 4]);
                mma1688(acc[0][nt], a[0], b0, b1);
                mma1688(acc[1][nt], a[1], b0, b1);
            }
        }
    };

    const int NIT = HH * (NN / 32);   // 512
    prod(0, 0); cp_commit();
    for (int i = 0; i < NIT; i++) {
        int s = i & 1;
        if (i + 1 < NIT) { prod(i + 1, s ^ 1); cp_commit(); cp_wait<1>(); }
        else cp_wait<0>();
        __syncthreads();
        domma(s);
        __syncthreads();
    }

#pragma unroll
    for (int mt = 0; mt < 2; mt++) {
#pragma unroll
        for (int nt = 0; nt < 8; nt++) {
            int row = n0 + warp_m * 32 + mt * 16 + g;
            int col = f0 + warp_n * 64 + nt * 8 + tg * 2;
            float2 v0, v1;
            v0.x = fmaxf(0.25f * acc[mt][nt][0], 0.f);
            v0.y = fmaxf(0.25f * acc[mt][nt][1], 0.f);
            v1.x = fmaxf(0.25f * acc[mt][nt][2], 0.f);
            v1.y = fmaxf(0.25f * acc[mt][nt][3], 0.f);
            *(float2*)(out + (size_t)row * FF + col) = v0;
            *(float2*)(out + (size_t)(row + 8) * FF + col) = v1;
        }
    }
}

// ================= launch =================
extern "C" void kernel_launch(void* const* d_in, const int* in_sizes, int n_in,
                              void* d_out, int out_size)
{
    const float* nodes  = (const float*)d_in[0];
    const float* edges  = (const float*)d_in[1];
    const float* labels = (const float*)d_in[2];
    const float* We     = (const float*)d_in[3];
    const float* be     = (const float*)d_in[4];
    const float* Wm     = (const float*)d_in[5];
    const float* b      = (const float*)d_in[6];
    const float* u      = (const float*)d_in[7];
    const float* v      = (const float*)d_in[8];
    float* out = (float*)d_out;

    static bool attr_done = false;
    if (!attr_done) {
        cudaFuncSetAttribute(feats_gemm, cudaFuncAttributeMaxDynamicSharedMemorySize, F_SMEM);
        cudaFuncSetAttribute(attn_gemm, cudaFuncAttributeMaxDynamicSharedMemorySize, A_SMEM);
        attr_done = true;
    }

    build_A<<<NN * DD / 4 / 256, 256>>>(nodes, edges, labels);
    build_BT<<<dim3(KK / 32, FF / 32, HH), 256>>>(Wm, We);
    build_bias2<<<HH * FF / 256, 256>>>(b, be);
    feats_gemm<<<dim3(FF / 128, NN / 128, HH), 256, F_SMEM>>>();  // profile slot
    wuwv_kernel<<<HH * DD / 8, 256>>>(Wm, u, v);
    bubv_kernel<<<1, 128>>>(b, u, v);
    st_kernel<<<HH * NN / 8, 256>>>(nodes);
    minmax_kernel<<<HH, 256>>>();
    z_kernel<<<HH * NN / 8, 256>>>();
    attn_gemm<<<dim3(FF / 128, NN / 128), 256, A_SMEM>>>(out);
}

// round 9
// speedup vs baseline: 2.9350x; 1.1773x over previous
#include <cuda_runtime.h>
#include <cstdint>

#define NN 4096
#define DD 512
#define FF 512
#define HH 4
#define KK 1024
#define ALPHA 0.3f
#define L2E 1.4426950408889634f

// ---- scratch (device globals; no allocation allowed) ----
__device__ float g_A[NN * KK];          // tf32-rounded [nodes | edges+labels], [m][k]
__device__ float g_BT[HH * FF * KK];    // tf32-rounded [h][f][k] = [W^T | We^T]
__device__ float g_bias2[HH * FF];
__device__ float g_featsT[(size_t)HH * FF * NN];  // [h][f][m], tf32-rounded
__device__ float g_s[HH * NN];
__device__ float g_t[HH * NN];
__device__ float g_rmax[HH * NN];
__device__ float g_invz[HH * NN];
__device__ float g_wu[HH * DD];
__device__ float g_wv[HH * DD];
__device__ float g_bu[HH];
__device__ float g_bv[HH];
__device__ float g_hpmax[HH];
__device__ float g_hmmin[HH];

// ================= helpers =================
__device__ __forceinline__ float warp_sum(float x) {
#pragma unroll
    for (int o = 16; o > 0; o >>= 1) x += __shfl_xor_sync(0xffffffffu, x, o);
    return x;
}
__device__ __forceinline__ uint32_t cvt_tf32(float x) {
    uint32_t r; asm("cvt.rna.tf32.f32 %0, %1;" : "=r"(r) : "f"(x)); return r;
}
__device__ __forceinline__ float tf32r(float x) {
    return __uint_as_float(cvt_tf32(x));
}
// 2^y on the MUFU pipe (consistent between z_kernel and weight gen)
__device__ __forceinline__ float fex2(float y) {
    float r; asm("ex2.approx.ftz.f32 %0, %1;" : "=f"(r) : "f"(y)); return r;
}
__device__ __forceinline__ uint32_t smem_u32(const void* p) {
    uint32_t a;
    asm("{ .reg .u64 t; cvta.to.shared.u64 t, %1; cvt.u32.u64 %0, t; }"
        : "=r"(a) : "l"(p));
    return a;
}
__device__ __forceinline__ void cpasync16(uint32_t dst, const void* src) {
    asm volatile("cp.async.cg.shared.global [%0], [%1], 16;" :: "r"(dst), "l"(src));
}
__device__ __forceinline__ void cp_commit() {
    asm volatile("cp.async.commit_group;" ::: "memory");
}
template <int N>
__device__ __forceinline__ void cp_wait() {
    asm volatile("cp.async.wait_group %0;" :: "n"(N) : "memory");
}
__device__ __forceinline__ void mma1688(float* c, const uint32_t* a, uint32_t b0, uint32_t b1) {
    asm volatile(
        "mma.sync.aligned.m16n8k8.row.col.f32.tf32.tf32.f32 "
        "{%0,%1,%2,%3}, {%4,%5,%6,%7}, {%8,%9}, {%0,%1,%2,%3};"
        : "+f"(c[0]), "+f"(c[1]), "+f"(c[2]), "+f"(c[3])
        : "r"(a[0]), "r"(a[1]), "r"(a[2]), "r"(a[3]), "r"(b0), "r"(b1));
}

// ================= fused setup kernel =================
// blocks [0, 2048)        : build_A     (float4 per thread: 2048*256*4 = NN*DD)
// blocks [2048, 4096)     : build_BT    (tiled transpose)
// blocks [4096, 4104)     : bias2
// blocks [4104, 4360)     : wuwv
// block  4360             : bubv
#define SETUP_BLOCKS 4361

__global__ __launch_bounds__(256) void setup_kernel(
    const float* __restrict__ nodes, const float* __restrict__ edges,
    const float* __restrict__ labels, const float* __restrict__ W,
    const float* __restrict__ We, const float* __restrict__ b,
    const float* __restrict__ be, const float* __restrict__ u,
    const float* __restrict__ v)
{
    __shared__ float tile[32][33];
    int bx = blockIdx.x;
    int tid = threadIdx.x;
    if (bx < 2048) {
        int i = bx * 256 + tid;           // float4 index over NN*DD/4
        int m = i >> 7, dq = i & 127;
        float4 a = ((const float4*)nodes)[i];
        float4 x = ((const float4*)edges)[i];
        float4 y = ((const float4*)labels)[i];
        float* h0 = g_A + (size_t)m * KK + dq * 4;
        float av[4] = {a.x, a.y, a.z, a.w};
        float cv[4] = {x.x + y.x, x.y + y.y, x.z + y.z, x.w + y.w};
#pragma unroll
        for (int j = 0; j < 4; j++) {
            h0[j] = tf32r(av[j]);
            h0[DD + j] = tf32r(cv[j]);
        }
    } else if (bx < 4096) {
        int jb = bx - 2048;               // 2048 = HH * 32 * 16
        int h = jb >> 9;
        int r = jb & 511;
        int k0 = (r >> 4) * 32, f0 = (r & 15) * 32;
        int tx = tid & 31, ty0 = tid >> 5;
#pragma unroll
        for (int j = 0; j < 4; j++) {
            int ty = ty0 * 4 + j;
            int k = k0 + ty;
            float vv = (k < DD) ? W[((size_t)h * DD + k) * FF + f0 + tx]
                                : We[(size_t)(k - DD) * FF + f0 + tx];
            tile[ty][tx] = vv;
        }
        __syncthreads();
#pragma unroll
        for (int j = 0; j < 4; j++) {
            int ty = ty0 * 4 + j;
            g_BT[((size_t)h * FF + f0 + ty) * KK + k0 + tx] = tf32r(tile[tx][ty]);
        }
    } else if (bx < 4104) {
        int i = (bx - 4096) * 256 + tid;  // HH*FF = 2048
        int f = i & (FF - 1);
        g_bias2[i] = b[i] + be[f];
    } else if (bx < 4360) {
        int w = (bx - 4104) * 8 + (tid >> 5);   // HH*DD = 2048 warps
        int lane = tid & 31;
        int h = w / DD, d = w % DD;
        const float4* Wr = (const float4*)(W + ((long)h * DD + d) * FF);
        const float4* up = (const float4*)(u + (long)h * FF);
        const float4* vp = (const float4*)(v + (long)h * FF);
        float su = 0.f, sv = 0.f;
        for (int i = lane; i < FF / 4; i += 32) {
            float4 w4 = Wr[i], u4 = up[i], v4 = vp[i];
            su += w4.x * u4.x + w4.y * u4.y + w4.z * u4.z + w4.w * u4.w;
            sv += w4.x * v4.x + w4.y * v4.y + w4.z * v4.z + w4.w * v4.w;
        }
        su = warp_sum(su); sv = warp_sum(sv);
        if (lane == 0) { g_wu[h * DD + d] = su; g_wv[h * DD + d] = sv; }
    } else {
        if (tid < 128) {
            int h = tid >> 5;
            int lane = tid & 31;
            float su = 0.f, sv = 0.f;
            for (int i = lane; i < FF; i += 32) {
                float bb = b[h * FF + i];
                su += bb * u[h * FF + i];
                sv += bb * v[h * FF + i];
            }
            su = warp_sum(su); sv = warp_sum(sv);
            if (lane == 0) { g_bu[h] = su; g_bv[h] = sv; }
        }
    }
}

// ================= rank-1 precomputation =================
__global__ __launch_bounds__(256) void st_kernel(const float* __restrict__ nodes) {
    int w = blockIdx.x * 8 + (threadIdx.x >> 5);
    int lane = threadIdx.x & 31;
    int h = w >> 12;
    int n = w & (NN - 1);
    const float4* nr = (const float4*)(nodes + (long)n * DD);
    const float4* wu = (const float4*)(g_wu + (long)h * DD);
    const float4* wv = (const float4*)(g_wv + (long)h * DD);
    float ss = 0.f, tt = 0.f;
    for (int i = lane; i < DD / 4; i += 32) {
        float4 x = nr[i], a = wu[i], c = wv[i];
        ss += x.x * a.x + x.y * a.y + x.z * a.z + x.w * a.w;
        tt += x.x * c.x + x.y * c.y + x.z * c.z + x.w * c.w;
    }
    ss = warp_sum(ss); tt = warp_sum(tt);
    if (lane == 0) {
        g_s[h * NN + n] = ss + g_bu[h];
        g_t[h * NN + n] = tt + g_bv[h];
    }
}

__global__ void minmax_kernel() {
    int h = blockIdx.x;
    int tid = threadIdx.x;
    __shared__ float smx[256], smn[256];
    float mx = -1e30f, mn = 1e30f;
    for (int m = tid; m < NN; m += 256) {
        float t = g_t[h * NN + m];
        float hp = t >= 0.f ? t : ALPHA * t;
        float hm = t <= 0.f ? t : ALPHA * t;
        mx = fmaxf(mx, hp);
        mn = fminf(mn, hm);
    }
    smx[tid] = mx; smn[tid] = mn;
    __syncthreads();
    for (int sft = 128; sft > 0; sft >>= 1) {
        if (tid < sft) {
            smx[tid] = fmaxf(smx[tid], smx[tid + sft]);
            smn[tid] = fminf(smn[tid], smn[tid + sft]);
        }
        __syncthreads();
    }
    if (tid == 0) { g_hpmax[h] = smx[0]; g_hmmin[h] = smn[0]; }
}

__global__ __launch_bounds__(256) void z_kernel() {
    int w = blockIdx.x * 8 + (threadIdx.x >> 5);
    int lane = threadIdx.x & 31;
    int h = w >> 12, n = w & (NN - 1);
    float s = g_s[h * NN + n];
    float rmax = s > 0.f ? s * g_hpmax[h] : (s < 0.f ? s * g_hmmin[h] : 0.f);
    const float* tp = g_t + (long)h * NN;
    float z = 0.f;
    for (int m = lane; m < NN; m += 32) {
        float sc = s * tp[m];
        sc = sc >= 0.f ? sc : ALPHA * sc;
        z += fex2(fmaxf((sc - rmax) * L2E, -126.f));
    }
    z = warp_sum(z);
    if (lane == 0) {
        g_rmax[h * NN + n] = rmax;
        g_invz[h * NN + n] = 1.f / z;
    }
}

// ================= feats GEMM (mma.sync tf32, 3-stage) =================
#define F_AS 4608                  // 128*36 floats
#define F_STG 9216                 // As + Bs
#define F_SMEM (3 * F_STG * 4)     // 110592 bytes

__global__ __launch_bounds__(256) void feats_gemm() {
    extern __shared__ float sm[];
    int tid = threadIdx.x, wid = tid >> 5, lane = tid & 31;
    int g = lane >> 2, tg = lane & 3;
    int h = blockIdx.z;
    int m0 = blockIdx.y * 128, f0 = blockIdx.x * 128;
    const float* Bp = g_BT + (size_t)h * FF * KK;
    int warp_m = wid & 3, warp_n = wid >> 2;

    float acc[2][8][4];
#pragma unroll
    for (int a = 0; a < 2; a++)
#pragma unroll
        for (int bq = 0; bq < 8; bq++)
#pragma unroll
            for (int c = 0; c < 4; c++) acc[a][bq][c] = 0.f;

    int prow = tid & 127, pseg = tid >> 7;

    auto prod = [&](int c, int s) {
        float* As = sm + s * F_STG;
        float* Bs = As + F_AS;
        int k0 = c * 32;
        const float* asrc = g_A + (size_t)(m0 + prow) * KK + k0 + pseg * 16;
        const float* bsrc = Bp + (size_t)(f0 + prow) * KK + k0 + pseg * 16;
        uint32_t ad = smem_u32(As + prow * 36 + pseg * 16);
        uint32_t bd = smem_u32(Bs + prow * 36 + pseg * 16);
#pragma unroll
        for (int j = 0; j < 4; j++) {
            cpasync16(ad + j * 16, asrc + j * 4);
            cpasync16(bd + j * 16, bsrc + j * 4);
        }
    };
    auto domma = [&](int s) {
        float* As = sm + s * F_STG;
        float* Bs = As + F_AS;
#pragma unroll
        for (int ks = 0; ks < 4; ks++) {
            uint32_t a[2][4];
#pragma unroll
            for (int mt = 0; mt < 2; mt++) {
                int base = warp_m * 32 + mt * 16;
                a[mt][0] = __float_as_uint(As[(base + g) * 36 + ks * 8 + tg]);
                a[mt][1] = __float_as_uint(As[(base + 8 + g) * 36 + ks * 8 + tg]);
                a[mt][2] = __float_as_uint(As[(base + g) * 36 + ks * 8 + tg + 4]);
                a[mt][3] = __float_as_uint(As[(base + 8 + g) * 36 + ks * 8 + tg + 4]);
            }
#pragma unroll
            for (int nt = 0; nt < 8; nt++) {
                int fc = warp_n * 64 + nt * 8 + g;
                uint32_t b0 = __float_as_uint(Bs[fc * 36 + ks * 8 + tg]);
                uint32_t b1 = __float_as_uint(Bs[fc * 36 + ks * 8 + tg + 4]);
                mma1688(acc[0][nt], a[0], b0, b1);
                mma1688(acc[1][nt], a[1], b0, b1);
            }
        }
    };

    const int NIT = KK / 32;   // 32
    prod(0, 0); cp_commit();
    prod(1, 1); cp_commit();
    cp_wait<1>();
    __syncthreads();
    for (int i = 0; i < NIT; i++) {
        domma(i % 3);
        if (i + 2 < NIT) { prod(i + 2, (i + 2) % 3); cp_commit(); cp_wait<1>(); }
        else if (i + 2 == NIT) cp_wait<0>();
        __syncthreads();
    }

    float* dst = g_featsT + (size_t)h * FF * NN;
#pragma unroll
    for (int mt = 0; mt < 2; mt++) {
#pragma unroll
        for (int nt = 0; nt < 8; nt++) {
            int row = m0 + warp_m * 32 + mt * 16 + g;
            int col = f0 + warp_n * 64 + nt * 8 + tg * 2;
            float b0v = g_bias2[h * FF + col];
            float b1v = g_bias2[h * FF + col + 1];
            dst[(size_t)col * NN + row]           = tf32r(acc[mt][nt][0] + b0v);
            dst[(size_t)(col + 1) * NN + row]     = tf32r(acc[mt][nt][1] + b1v);
            dst[(size_t)col * NN + row + 8]       = tf32r(acc[mt][nt][2] + b0v);
            dst[(size_t)(col + 1) * NN + row + 8] = tf32r(acc[mt][nt][3] + b1v);
        }
    }
}

// ================= fused attention GEMM (mma.sync tf32, 3-stage) =================
// CTA tile 64n x 128f, grid (4 f, 64 n) = 256 CTAs -> 2 per SM.
// 8 warps as 2m x 4n; warp tile 32n x 32f.
// w = 2^( s_n*t_m * (>=0 ? L2E : 0.3*L2E) + C_n ),  C_n = log2(invz_n) - rmax_n*L2E
#define A_CONST 512                // s_sm[256] + c_sm[256]
#define A_AS 2304                  // 64*36
#define A_STG (A_AS + 4608)        // As + Bs(128*36) = 6912
#define A_SMEM ((A_CONST + 3 * A_STG) * 4)   // 84992 bytes

__global__ __launch_bounds__(256) void attn_gemm(float* __restrict__ out) {
    extern __shared__ float sm[];
    float* s_sm = sm;              // [4h][64]
    float* c_sm = sm + 256;        // [4h][64]
    int tid = threadIdx.x, wid = tid >> 5, lane = tid & 31;
    int g = lane >> 2, tg = lane & 3;
    int n0 = blockIdx.y * 64, f0 = blockIdx.x * 128;
    int warp_m = wid & 1, warp_n = wid >> 1;

    {
        int hh = tid >> 6, nl = tid & 63;     // 256 = 4*64
        float iz = g_invz[hh * NN + n0 + nl];
        float rm = g_rmax[hh * NN + n0 + nl];
        s_sm[tid] = g_s[hh * NN + n0 + nl];
        c_sm[tid] = __log2f(iz) - rm * L2E;
    }

    float acc[2][4][4];
#pragma unroll
    for (int a = 0; a < 2; a++)
#pragma unroll
        for (int bq = 0; bq < 4; bq++)
#pragma unroll
            for (int c = 0; c < 4; c++) acc[a][bq][c] = 0.f;

    int nloc = tid & 63, kq = tid >> 6;       // weight gen: 8 k's each
    int prow = tid & 127, pseg = tid >> 7;    // B copy

    auto prod = [&](int c, int s) {
        float* As = sm + A_CONST + s * A_STG;
        float* Bs = As + A_AS;
        int h = c >> 7;
        int m0 = (c & 127) << 5;
        float sv = s_sm[h * 64 + nloc];
        float cn = c_sm[h * 64 + nloc];
        const float4* tp = (const float4*)(g_t + h * NN + m0 + kq * 8);
        float w[8];
#pragma unroll
        for (int q = 0; q < 2; q++) {
            float4 t4 = __ldg(tp + q);
            float tv[4] = {t4.x, t4.y, t4.z, t4.w};
#pragma unroll
            for (int r = 0; r < 4; r++) {
                float sc = sv * tv[r];
                float mult = sc >= 0.f ? L2E : (ALPHA * L2E);
                float y = fmaxf(fmaf(sc, mult, cn), -126.f);
                w[q * 4 + r] = tf32r(fex2(y));
            }
        }
        float* d = As + nloc * 36 + kq * 8;
        *(float4*)d       = make_float4(w[0], w[1], w[2], w[3]);
        *(float4*)(d + 4) = make_float4(w[4], w[5], w[6], w[7]);
        const float* bsrc = g_featsT + (size_t)h * FF * NN
                          + (size_t)(f0 + prow) * NN + m0 + pseg * 16;
        uint32_t bd = smem_u32(Bs + prow * 36 + pseg * 16);
#pragma unroll
        for (int j = 0; j < 4; j++) cpasync16(bd + j * 16, bsrc + j * 4);
    };
    auto domma = [&](int s) {
        float* As = sm + A_CONST + s * A_STG;
        float* Bs = As + A_AS;
#pragma unroll
        for (int ks = 0; ks < 4; ks++) {
            uint32_t a[2][4];
#pragma unroll
            for (int mt = 0; mt < 2; mt++) {
                int base = warp_m * 32 + mt * 16;
                a[mt][0] = __float_as_uint(As[(base + g) * 36 + ks * 8 + tg]);
                a[mt][1] = __float_as_uint(As[(base + 8 + g) * 36 + ks * 8 + tg]);
                a[mt][2] = __float_as_uint(As[(base + g) * 36 + ks * 8 + tg + 4]);
                a[mt][3] = __float_as_uint(As[(base + 8 + g) * 36 + ks * 8 + tg + 4]);
            }
#pragma unroll
            for (int nt = 0; nt < 4; nt++) {
                int fc = warp_n * 32 + nt * 8 + g;
                uint32_t b0 = __float_as_uint(Bs[fc * 36 + ks * 8 + tg]);
                uint32_t b1 = __float_as_uint(Bs[fc * 36 + ks * 8 + tg + 4]);
                mma1688(acc[0][nt], a[0], b0, b1);
                mma1688(acc[1][nt], a[1], b0, b1);
            }
        }
    };

    const int NIT = HH * (NN / 32);   // 512
    __syncthreads();                  // s_sm/c_sm ready (prod reads them)
    prod(0, 0); cp_commit();
    prod(1, 1); cp_commit();
    cp_wait<1>();
    __syncthreads();
    for (int i = 0; i < NIT; i++) {
        domma(i % 3);
        if (i + 2 < NIT) { prod(i + 2, (i + 2) % 3); cp_commit(); cp_wait<1>(); }
        else if (i + 2 == NIT) cp_wait<0>();
        __syncthreads();
    }

#pragma unroll
    for (int mt = 0; mt < 2; mt++) {
#pragma unroll
        for (int nt = 0; nt < 4; nt++) {
            int row = n0 + warp_m * 32 + mt * 16 + g;
            int col = f0 + warp_n * 32 + nt * 8 + tg * 2;
            float2 v0, v1;
            v0.x = fmaxf(0.25f * acc[mt][nt][0], 0.f);
            v0.y = fmaxf(0.25f * acc[mt][nt][1], 0.f);
            v1.x = fmaxf(0.25f * acc[mt][nt][2], 0.f);
            v1.y = fmaxf(0.25f * acc[mt][nt][3], 0.f);
            *(float2*)(out + (size_t)row * FF + col) = v0;
            *(float2*)(out + (size_t)(row + 8) * FF + col) = v1;
        }
    }
}

// ================= launch =================
extern "C" void kernel_launch(void* const* d_in, const int* in_sizes, int n_in,
                              void* d_out, int out_size)
{
    const float* nodes  = (const float*)d_in[0];
    const float* edges  = (const float*)d_in[1];
    const float* labels = (const float*)d_in[2];
    const float* We     = (const float*)d_in[3];
    const float* be     = (const float*)d_in[4];
    const float* Wm     = (const float*)d_in[5];
    const float* b      = (const float*)d_in[6];
    const float* u      = (const float*)d_in[7];
    const float* v      = (const float*)d_in[8];
    float* out = (float*)d_out;

    static bool attr_done = false;
    if (!attr_done) {
        cudaFuncSetAttribute(feats_gemm, cudaFuncAttributeMaxDynamicSharedMemorySize, F_SMEM);
        cudaFuncSetAttribute(attn_gemm, cudaFuncAttributeMaxDynamicSharedMemorySize, A_SMEM);
        attr_done = true;
    }

    setup_kernel<<<SETUP_BLOCKS, 256>>>(nodes, edges, labels, Wm, We, b, be, u, v);
    st_kernel<<<HH * NN / 8, 256>>>(nodes);
    minmax_kernel<<<HH, 256>>>();
    feats_gemm<<<dim3(FF / 128, NN / 128, HH), 256, F_SMEM>>>();  // capture slot 4
    z_kernel<<<HH * NN / 8, 256>>>();
    attn_gemm<<<dim3(FF / 128, NN / 64), 256, A_SMEM>>>(out);
}